// round 8
// baseline (speedup 1.0000x reference)
#include <cuda_runtime.h>
#include <cuda_bf16.h>

#define BN 64
#define SEQ 48
#define HD 256
#define MM 193
#define TSTEPS 96

// ------------- device scratch -------------
__device__ float g_B [BN*SEQ*HD];
__device__ float g_sb[BN*SEQ];
__device__ float g_V [BN*MM*HD];
__device__ float g_s [BN*MM];
__device__ float g_c [BN*HD];
__device__ float g_At [1024*BN];   // k-major activations [xb|x1|x2|h]
__device__ float g_A2t[512*BN];    // k-major [r1|r2]
__device__ float g_Wf[1024*1024];  // [k][j] fused wih|whh
__device__ float g_bf[1024];
__device__ float g_Wt[512*1280];   // [k][j] fused lw|rw
__device__ float g_bt[1280];
__device__ float g_Wm0[256*1024];
__device__ float g_Wm1[1024*1024];
__device__ float g_Gp[16*BN*1024];
__device__ float g_Tp[8*BN*1280];
__device__ float g_y0[BN*1024];
__device__ float g_y1[BN*1024];
__device__ int   g_is64;

__device__ __forceinline__ float sigf(float x){ return 1.f/(1.f+expf(-x)); }

#define FMA2(d,a,b) asm("fma.rn.f32x2 %0, %1, %2, %0;" : "+l"(d) : "l"(a), "l"(b))

// ------------- warp scans (with nonzero-range tracking) -------------
__device__ __forceinline__ void scan_stack(float* srow, float a, float* w1, float* wt,
                                           bool pop, int* mEnd){
  int lane = threadIdx.x & 31;
  float run = 0.f;
  #pragma unroll
  for (int c = 0; c < 7; c++){
    int m = c*32 + lane;
    float sv = (m < MM) ? srow[m] : 0.f;
    float v = sv;
    #pragma unroll
    for (int o = 1; o < 32; o <<= 1){
      float n = __shfl_up_sync(0xffffffffu, v, o);
      if (lane >= o) v += n;
    }
    float Pm = run + v, Pp = Pm - sv;
    float u1 = fminf(Pm, a) - fminf(Pp, a);
    float ut = fminf(Pm, 1.f + a) - fminf(Pp, 1.f + a);
    if (m < MM){
      w1[m] = u1; wt[m] = ut;
      if (pop) srow[m] = sv - ut;
      if (ut > 0.f) atomicMax(mEnd, m + 1);
    }
    run += __shfl_sync(0xffffffffu, v, 31);
  }
  __syncwarp();
}

__device__ __forceinline__ void scan_buf(float* srow, float a, float* wb,
                                         bool pop, int* bEnd){
  int lane = threadIdx.x & 31;
  float run = 0.f;
  #pragma unroll
  for (int c = 0; c < 2; c++){
    int m = c*32 + lane;
    float sv = (m < SEQ) ? srow[m] : 0.f;
    float v = sv;
    #pragma unroll
    for (int o = 1; o < 32; o <<= 1){
      float n = __shfl_up_sync(0xffffffffu, v, o);
      if (lane >= o) v += n;
    }
    float Pm = run + v, Pp = Pm - sv;
    float w = fminf(Pm, a) - fminf(Pp, a);
    if (m < SEQ){
      wb[m] = w;
      if (pop) srow[m] = sv - w;
      if (w > 0.f) atomicMax(bEnd, m + 1);
    }
    run += __shfl_sync(0xffffffffu, v, 31);
  }
  __syncwarp();
}

// ------------- token dtype detect -------------
__global__ void k_tok(const void* x){
  __shared__ int ok;
  if (threadIdx.x == 0) ok = 1;
  __syncthreads();
  const long long* xl = (const long long*)x;
  int bad = 0;
  for (int i = threadIdx.x; i < (BN*SEQ)/2; i += 256){
    long long v = xl[i];
    if (v < 0 || v >= 50257) bad = 1;
  }
  if (bad) atomicAnd(&ok, 0);
  __syncthreads();
  if (threadIdx.x == 0) g_is64 = ok;
}

// ------------- prep -------------
__global__ void k_prep(const void* x, const float* emb,
                       const float* wih, const float* whh,
                       const float* bih, const float* bhh,
                       const float* lw, const float* lb,
                       const float* rw, const float* rb,
                       const float* l0w, const float* l1w){
  int gid = blockIdx.x*blockDim.x + threadIdx.x;
  int gsz = gridDim.x*blockDim.x;
  int is64 = g_is64;
  const long long* xl = (const long long*)x;
  const int* xi = (const int*)x;
  for (int i = gid; i < BN*SEQ; i += gsz){
    long long tok = is64 ? xl[i] : (long long)xi[i];
    g_sb[i] = (tok > 0) ? 1.f : 0.f;
  }
  for (int i = gid; i < BN*SEQ*HD; i += gsz){
    int row = i >> 8;
    long long tok = is64 ? xl[row] : (long long)xi[row];
    g_B[i] = emb[(size_t)tok*HD + (i & 255)];
  }
  for (int i = gid; i < 1024*1024; i += gsz){
    int k = i >> 10, j = i & 1023;
    g_Wf[i] = (k < 768) ? wih[j*768 + k] : whh[j*256 + (k-768)];
  }
  for (int i = gid; i < 512*1280; i += gsz){
    int k = i/1280, j = i%1280;
    g_Wt[i] = (k < 256) ? lw[j*256 + k] : rw[j*256 + (k-256)];
  }
  for (int i = gid; i < 1024; i += gsz) g_bf[i] = bih[i] + bhh[i];
  for (int i = gid; i < 1280; i += gsz) g_bt[i] = lb[i] + rb[i];
  for (int i = gid; i < 256*1024; i += gsz){ int k = i >> 10, j = i & 1023; g_Wm0[i] = l0w[j*256 + k]; }
  for (int i = gid; i < 1024*1024; i += gsz){ int k = i >> 10, j = i & 1023; g_Wm1[i] = l1w[j*1024 + k]; }
  for (int i = gid; i < BN*MM*HD; i += gsz) g_V[i] = 0.f;
  for (int i = gid; i < BN*MM; i += gsz) g_s[i] = 0.f;
  for (int i = gid; i < 1024*BN; i += gsz) g_At[i] = 0.f;
  for (int i = gid; i < BN*HD; i += gsz) g_c[i] = 0.f;
}

// ------------- f32x2 GEMM, splatted-A smem (no MOV splats) -------------
// tile 64b x 64j, k-slice 64 (4 chunks of 16), micro 4b x 4j, 256 thr, 2 CTA/SM
template<int J, int NKS>
__device__ __forceinline__ void gemm_body5(const float* __restrict__ At,
                                           const float* __restrict__ W,
                                           float* __restrict__ P){
  const int jt = blockIdx.x / NKS, ks = blockIdx.x % NKS;
  const int j0 = jt*64, k0 = ks*64;
  __shared__ float sA[2][16][128];   // duplicated: [2*b]=[2*b+1]=a
  __shared__ float sW[2][16][64];
  const int tid = threadIdx.x;
  const int tx = tid & 15;          // j group (4 floats)
  const int ty = tid >> 4;          // b group (4 floats)
  const int aK = tid >> 4, aF = tid & 15;
  const float* gA = At + (k0 + aK)*64 + 4*aF;
  const float* gW = W + (size_t)(k0 + aK)*J + j0 + 4*aF;

  float4 ra = *(const float4*)gA;
  float4 rw = *(const float4*)gW;

  unsigned long long acc[4][2];
  #pragma unroll
  for (int i = 0; i < 4; i++){ acc[i][0] = 0ull; acc[i][1] = 0ull; }

  {
    float4 lo = make_float4(ra.x, ra.x, ra.y, ra.y);
    float4 hi = make_float4(ra.z, ra.z, ra.w, ra.w);
    *(float4*)&sA[0][aK][8*aF]     = lo;
    *(float4*)&sA[0][aK][8*aF + 4] = hi;
    *(float4*)&sW[0][aK][4*aF]     = rw;
  }
  __syncthreads();

  #pragma unroll 1
  for (int c = 0; c < 4; c++){
    const int p = c & 1;
    if (c < 3){
      ra = *(const float4*)(gA + (c+1)*16*64);
      rw = *(const float4*)(gW + (size_t)((c+1)*16)*J);
    }
    #pragma unroll
    for (int kk = 0; kk < 16; kk++){
      ulonglong2 A01 = *(const ulonglong2*)&sA[p][kk][8*ty];
      ulonglong2 A23 = *(const ulonglong2*)&sA[p][kk][8*ty + 4];
      ulonglong2 w   = *(const ulonglong2*)&sW[p][kk][4*tx];
      FMA2(acc[0][0],A01.x,w.x); FMA2(acc[0][1],A01.x,w.y);
      FMA2(acc[1][0],A01.y,w.x); FMA2(acc[1][1],A01.y,w.y);
      FMA2(acc[2][0],A23.x,w.x); FMA2(acc[2][1],A23.x,w.y);
      FMA2(acc[3][0],A23.y,w.x); FMA2(acc[3][1],A23.y,w.y);
    }
    if (c < 3){
      __syncthreads();
      float4 lo = make_float4(ra.x, ra.x, ra.y, ra.y);
      float4 hi = make_float4(ra.z, ra.z, ra.w, ra.w);
      *(float4*)&sA[1-p][aK][8*aF]     = lo;
      *(float4*)&sA[1-p][aK][8*aF + 4] = hi;
      *(float4*)&sW[1-p][aK][4*aF]     = rw;
      __syncthreads();
    }
  }
  #pragma unroll
  for (int i = 0; i < 4; i++){
    int b = 4*ty + i;
    ulonglong2 u; u.x = acc[i][0]; u.y = acc[i][1];
    *(ulonglong2*)&P[(size_t)(ks*64 + b)*J + j0 + 4*tx] = u;
  }
}

__global__ void __launch_bounds__(256,2) k_lstm(){ gemm_body5<1024,16>(g_At,  g_Wf, g_Gp); }
__global__ void __launch_bounds__(256,2) k_tree(){ gemm_body5<1280, 8>(g_A2t, g_Wt, g_Tp); }

// ------------- pointwise: gates, alphas, popping reads -------------
__global__ void __launch_bounds__(256) k_point(int t, int m0, const float* __restrict__ aw,
                                               const float* __restrict__ ab){
  int b = blockIdx.x, tid = threadIdx.x, warp = tid >> 5, lane = tid & 31;
  __shared__ float sg[1024], w1[224], wt[224], wb[64], red[16];
  __shared__ float s_ar;
  __shared__ int mEnd, bEnd;
  if (tid == 0){ mEnd = m0; bEnd = 0; }
  for (int j = tid; j < 1024; j += 256){
    float v = g_bf[j];
    #pragma unroll
    for (int ks = 0; ks < 16; ks++) v += g_Gp[(size_t)(ks*64 + b)*1024 + j];
    sg[j] = v;
  }
  __syncthreads();
  {
    int h = tid;
    float gi = sg[h], gf = sg[256+h], gg = sg[512+h], go = sg[768+h];
    float c = g_c[b*HD + h];
    c = sigf(gf)*c + sigf(gi)*tanhf(gg);
    float hh = sigf(go)*tanhf(c);
    g_c[b*HD + h] = c;
    g_At[(768+h)*64 + b] = hh;
    float p0 = hh*aw[h], p1 = hh*aw[256+h];
    #pragma unroll
    for (int o = 16; o >= 1; o >>= 1){
      p0 += __shfl_xor_sync(0xffffffffu, p0, o);
      p1 += __shfl_xor_sync(0xffffffffu, p1, o);
    }
    if (lane == 0){ red[warp] = p0; red[8+warp] = p1; }
  }
  __syncthreads();
  if (tid == 0){
    float d0 = ab[0], d1 = ab[1];
    for (int w = 0; w < 8; w++){ d0 += red[w]; d1 += red[8+w]; }
    s_ar = sigf(10.f*(d0 - d1));
  }
  __syncthreads();
  float ar = s_ar, as = 1.f - ar;
  int idx = 191 - 2*t, idx2 = 190 - 2*t;
  if (warp == 0){
    scan_stack(&g_s[b*MM], ar, w1, wt, true, &mEnd);
    if (lane == 0){ g_s[b*MM + idx] = ar; g_s[b*MM + idx2] = as; }
  } else if (warp == 1){
    scan_buf(&g_sb[b*SEQ], as, wb, true, &bEnd);
  }
  __syncthreads();
  {
    int h = tid;
    int me = mEnd, be = bEnd;
    float r1 = 0.f, r2 = 0.f;
    const float* Vb = g_V + (b*MM)*HD + h;
    for (int m = m0; m < me; m++){
      float tw = wt[m];
      if (tw != 0.f){
        float v = Vb[m*HD];
        r1 = fmaf(w1[m], v, r1);
        r2 = fmaf(tw - w1[m], v, r2);
      }
    }
    g_A2t[h*64 + b] = r1;
    g_A2t[(256+h)*64 + b] = r2;
    float bv = 0.f;
    const float* Bb = g_B + (b*SEQ)*HD + h;
    for (int s2 = 0; s2 < be; s2++){
      float w = wb[s2];
      if (w != 0.f) bv = fmaf(w, Bb[s2*HD], bv);
    }
    g_V[(b*MM + idx2)*HD + h] = bv;
  }
}

// ------------- epilogue: tree cell + next-step alpha=1 reads -------------
__global__ void __launch_bounds__(256) k_epi(int t, int m0){
  int b = blockIdx.x, tid = threadIdx.x, warp = tid >> 5;
  __shared__ float stg[1280], w1[224], wt[224], wb[64];
  __shared__ int mEnd, bEnd;
  if (tid == 0){ mEnd = m0; bEnd = 0; }
  __syncthreads();
  if (t >= 0){
    for (int j = tid; j < 1280; j += 256){
      float v = g_bt[j];
      #pragma unroll
      for (int ks = 0; ks < 8; ks++) v += g_Tp[(size_t)(ks*64 + b)*1280 + j];
      stg[j] = v;
    }
    __syncthreads();
    int h = tid;
    float ta = stg[h], ti = stg[256+h], f1 = stg[512+h], f2 = stg[768+h], to = stg[1024+h];
    float r1 = g_A2t[h*64 + b], r2 = g_A2t[(256+h)*64 + b];
    float ct = tanhf(ta)*sigf(ti) + sigf(f1)*r1 + sigf(f2)*r2;
    float ht = sigf(to)*tanhf(ct);
    g_V[(b*MM + (191 - 2*t))*HD + h] = ht;
    __syncthreads();
  }
  if (warp == 0) scan_stack(&g_s[b*MM], 1.f, w1, wt, false, &mEnd);
  else if (warp == 1) scan_buf(&g_sb[b*SEQ], 1.f, wb, false, &bEnd);
  __syncthreads();
  int h = tid;
  int me = mEnd, be = bEnd;
  float xb = 0.f;
  const float* Bb = g_B + (b*SEQ)*HD + h;
  for (int s2 = 0; s2 < be; s2++){
    float w = wb[s2];
    if (w != 0.f) xb = fmaf(w, Bb[s2*HD], xb);
  }
  float x1 = 0.f, x2 = 0.f;
  const float* Vb = g_V + (b*MM)*HD + h;
  for (int m = m0; m < me; m++){
    float tw = wt[m];
    if (tw != 0.f){
      float v = Vb[m*HD];
      x1 = fmaf(w1[m], v, x1);
      x2 = fmaf(tw - w1[m], v, x2);
    }
  }
  g_At[h*64 + b] = xb;
  g_At[(256+h)*64 + b] = x1;
  g_At[(512+h)*64 + b] = x2;
}

// ------------- MLP head -------------
__global__ void __launch_bounds__(256) k_mlp0(const float* __restrict__ l0b){
  int b = blockIdx.x, tid = threadIdx.x;
  __shared__ float xs[256];
  xs[tid] = g_At[(256+tid)*64 + b];
  __syncthreads();
  float4 acc = *(const float4*)&l0b[4*tid];
  for (int k = 0; k < 256; k++){
    float4 w = *(const float4*)&g_Wm0[k*1024 + 4*tid];
    float x = xs[k];
    acc.x = fmaf(x, w.x, acc.x); acc.y = fmaf(x, w.y, acc.y);
    acc.z = fmaf(x, w.z, acc.z); acc.w = fmaf(x, w.w, acc.w);
  }
  acc.x = fmaxf(acc.x, 0.f); acc.y = fmaxf(acc.y, 0.f);
  acc.z = fmaxf(acc.z, 0.f); acc.w = fmaxf(acc.w, 0.f);
  *(float4*)&g_y0[b*1024 + 4*tid] = acc;
}

__global__ void __launch_bounds__(256) k_mlp1(const float* __restrict__ l1b){
  int b = blockIdx.x, tid = threadIdx.x;
  __shared__ float xs[1024];
  for (int i = tid; i < 1024; i += 256) xs[i] = g_y0[b*1024 + i];
  __syncthreads();
  float4 acc = *(const float4*)&l1b[4*tid];
  for (int k = 0; k < 1024; k++){
    float4 w = *(const float4*)&g_Wm1[k*1024 + 4*tid];
    float x = xs[k];
    acc.x = fmaf(x, w.x, acc.x); acc.y = fmaf(x, w.y, acc.y);
    acc.z = fmaf(x, w.z, acc.z); acc.w = fmaf(x, w.w, acc.w);
  }
  acc.x = fmaxf(acc.x, 0.f); acc.y = fmaxf(acc.y, 0.f);
  acc.z = fmaxf(acc.z, 0.f); acc.w = fmaxf(acc.w, 0.f);
  *(float4*)&g_y1[b*1024 + 4*tid] = acc;
}

__global__ void __launch_bounds__(256) k_mlp2(const float* __restrict__ l2w,
                                              const float* __restrict__ l2b,
                                              float* __restrict__ out){
  int b = blockIdx.x, tid = threadIdx.x, warp = tid >> 5, lane = tid & 31;
  __shared__ float red[8];
  for (int c = 0; c < 3; c++){
    float p = 0.f;
    for (int k = tid; k < 1024; k += 256)
      p = fmaf(g_y1[b*1024 + k], l2w[c*1024 + k], p);
    #pragma unroll
    for (int o = 16; o >= 1; o >>= 1) p += __shfl_xor_sync(0xffffffffu, p, o);
    if (lane == 0) red[warp] = p;
    __syncthreads();
    if (tid == 0){
      float s = l2b[c];
      for (int w = 0; w < 8; w++) s += red[w];
      out[b*3 + c] = s;
    }
    __syncthreads();
  }
}

// ------------- launch -------------
extern "C" void kernel_launch(void* const* d_in, const int* in_sizes, int n_in,
                              void* d_out, int out_size){
  const void*  x   = d_in[0];
  const float* emb = (const float*)d_in[1];
  const float* wih = (const float*)d_in[2];
  const float* whh = (const float*)d_in[3];
  const float* bih = (const float*)d_in[4];
  const float* bhh = (const float*)d_in[5];
  const float* aw  = (const float*)d_in[6];
  const float* ab  = (const float*)d_in[7];
  const float* lw  = (const float*)d_in[8];
  const float* lb  = (const float*)d_in[9];
  const float* rw  = (const float*)d_in[10];
  const float* rb  = (const float*)d_in[11];
  const float* l0w = (const float*)d_in[12];
  const float* l0b = (const float*)d_in[13];
  const float* l1w = (const float*)d_in[14];
  const float* l1b = (const float*)d_in[15];
  const float* l2w = (const float*)d_in[16];
  const float* l2b = (const float*)d_in[17];
  float* out = (float*)d_out;

  k_tok<<<1, 256>>>(x);
  k_prep<<<512, 256>>>(x, emb, wih, whh, bih, bhh, lw, lb, rw, rb, l0w, l1w);
  k_epi<<<64, 256>>>(-1, 192);
  for (int t = 0; t < TSTEPS; t++){
    int m0p = 192 - 2*t; if (m0p < 0) m0p = 0;
    int m0e = 190 - 2*t; if (m0e < 0) m0e = 0;
    k_lstm<<<256, 256>>>();
    k_point<<<64, 256>>>(t, m0p, aw, ab);
    k_tree<<<160, 256>>>();
    k_epi<<<64, 256>>>(t, m0e);
  }
  k_mlp0<<<64, 256>>>(l0b);
  k_mlp1<<<64, 256>>>(l1b);
  k_mlp2<<<64, 256>>>(l2w, l2b, out);
}

// round 9
// speedup vs baseline: 1.8649x; 1.8649x over previous
#include <cuda_runtime.h>
#include <cuda_bf16.h>

#define BN 64
#define SEQ 48
#define HD 256
#define MM 193
#define TSTEPS 96

// ------------- device scratch -------------
__device__ float g_B [BN*SEQ*HD];
__device__ float g_sb[BN*SEQ];
__device__ float g_V [BN*MM*HD];
__device__ float g_s [BN*MM];
__device__ float g_c [BN*HD];
// bf16 hi/lo weights, A-operand layout [j][k] (k contiguous)
__device__ __nv_bfloat16 g_Wfh[1024*1024], g_Wfl[1024*1024];
__device__ __nv_bfloat16 g_Wth[1280*512],  g_Wtl[1280*512];
// activations, k-pair packed: idx = (k>>1)*128 + 2*b + (k&1)
__device__ __nv_bfloat16 g_Aph [512*128], g_Apl [512*128];   // K=1024 (LSTM in)
__device__ __nv_bfloat16 g_A2ph[256*128], g_A2pl[256*128];   // K=512  (tree in)
__device__ float g_r12[BN*512];     // fp32 r1|r2 for tree cell
__device__ float g_x1f[BN*HD];      // fp32 x1 for MLP head
__device__ float g_bf[1024];
__device__ float g_bt[1280];
__device__ float g_Wm0[256*1024];
__device__ float g_Wm1[1024*1024];
__device__ float g_Gp[8*BN*1024];
__device__ float g_Tp[4*BN*1280];
__device__ float g_y0[BN*1024];
__device__ float g_y1[BN*1024];
__device__ int   g_is64;

__device__ __forceinline__ float sigf(float x){ return 1.f/(1.f+expf(-x)); }

__device__ __forceinline__ void packAct(__nv_bfloat16* Ah, __nv_bfloat16* Al,
                                        int k, int b, float v){
  __nv_bfloat16 hi = __float2bfloat16(v);
  float lo = v - __bfloat162float(hi);
  int idx = (k >> 1)*128 + 2*b + (k & 1);
  Ah[idx] = hi;
  Al[idx] = __float2bfloat16(lo);
}

#define MMA_BF16(D, A0,A1,A2,A3, B0,B1) \
  asm volatile("mma.sync.aligned.m16n8k16.row.col.f32.bf16.bf16.f32 " \
      "{%0,%1,%2,%3}, {%4,%5,%6,%7}, {%8,%9}, {%0,%1,%2,%3};" \
      : "+f"(D[0]),"+f"(D[1]),"+f"(D[2]),"+f"(D[3]) \
      : "r"(A0),"r"(A1),"r"(A2),"r"(A3),"r"(B0),"r"(B1))

// ------------- warp scans (with nonzero-range tracking) -------------
__device__ __forceinline__ void scan_stack(float* srow, float a, float* w1, float* wt,
                                           bool pop, int* mEnd){
  int lane = threadIdx.x & 31;
  float run = 0.f;
  #pragma unroll
  for (int c = 0; c < 7; c++){
    int m = c*32 + lane;
    float sv = (m < MM) ? srow[m] : 0.f;
    float v = sv;
    #pragma unroll
    for (int o = 1; o < 32; o <<= 1){
      float n = __shfl_up_sync(0xffffffffu, v, o);
      if (lane >= o) v += n;
    }
    float Pm = run + v, Pp = Pm - sv;
    float u1 = fminf(Pm, a) - fminf(Pp, a);
    float ut = fminf(Pm, 1.f + a) - fminf(Pp, 1.f + a);
    if (m < MM){
      w1[m] = u1; wt[m] = ut;
      if (pop) srow[m] = sv - ut;
      if (ut > 0.f) atomicMax(mEnd, m + 1);
    }
    run += __shfl_sync(0xffffffffu, v, 31);
  }
  __syncwarp();
}

__device__ __forceinline__ void scan_buf(float* srow, float a, float* wb,
                                         bool pop, int* bEnd){
  int lane = threadIdx.x & 31;
  float run = 0.f;
  #pragma unroll
  for (int c = 0; c < 2; c++){
    int m = c*32 + lane;
    float sv = (m < SEQ) ? srow[m] : 0.f;
    float v = sv;
    #pragma unroll
    for (int o = 1; o < 32; o <<= 1){
      float n = __shfl_up_sync(0xffffffffu, v, o);
      if (lane >= o) v += n;
    }
    float Pm = run + v, Pp = Pm - sv;
    float w = fminf(Pm, a) - fminf(Pp, a);
    if (m < SEQ){
      wb[m] = w;
      if (pop) srow[m] = sv - w;
      if (w > 0.f) atomicMax(bEnd, m + 1);
    }
    run += __shfl_sync(0xffffffffu, v, 31);
  }
  __syncwarp();
}

// ------------- token dtype detect -------------
__global__ void k_tok(const void* x){
  __shared__ int ok;
  if (threadIdx.x == 0) ok = 1;
  __syncthreads();
  const long long* xl = (const long long*)x;
  int bad = 0;
  for (int i = threadIdx.x; i < (BN*SEQ)/2; i += 256){
    long long v = xl[i];
    if (v < 0 || v >= 50257) bad = 1;
  }
  if (bad) atomicAnd(&ok, 0);
  __syncthreads();
  if (threadIdx.x == 0) g_is64 = ok;
}

// ------------- prep -------------
__global__ void k_prep(const void* x, const float* emb,
                       const float* wih, const float* whh,
                       const float* bih, const float* bhh,
                       const float* lw, const float* lb,
                       const float* rw, const float* rb,
                       const float* l0w, const float* l1w){
  int gid = blockIdx.x*blockDim.x + threadIdx.x;
  int gsz = gridDim.x*blockDim.x;
  int is64 = g_is64;
  const long long* xl = (const long long*)x;
  const int* xi = (const int*)x;
  for (int i = gid; i < BN*SEQ; i += gsz){
    long long tok = is64 ? xl[i] : (long long)xi[i];
    g_sb[i] = (tok > 0) ? 1.f : 0.f;
  }
  for (int i = gid; i < BN*SEQ*HD; i += gsz){
    int row = i >> 8;
    long long tok = is64 ? xl[row] : (long long)xi[row];
    g_B[i] = emb[(size_t)tok*HD + (i & 255)];
  }
  // LSTM weights: [j][k], k<768 from wih, else whh; bf16 hi/lo split
  for (int i = gid; i < 1024*1024; i += gsz){
    int j = i >> 10, k = i & 1023;
    float wv = (k < 768) ? wih[j*768 + k] : whh[j*256 + (k-768)];
    __nv_bfloat16 hi = __float2bfloat16(wv);
    g_Wfh[i] = hi;
    g_Wfl[i] = __float2bfloat16(wv - __bfloat162float(hi));
  }
  // tree weights: [j][k], k<256 from lw, else rw
  for (int i = gid; i < 1280*512; i += gsz){
    int j = i >> 9, k = i & 511;
    float wv = (k < 256) ? lw[j*256 + k] : rw[j*256 + (k-256)];
    __nv_bfloat16 hi = __float2bfloat16(wv);
    g_Wth[i] = hi;
    g_Wtl[i] = __float2bfloat16(wv - __bfloat162float(hi));
  }
  for (int i = gid; i < 1024; i += gsz) g_bf[i] = bih[i] + bhh[i];
  for (int i = gid; i < 1280; i += gsz) g_bt[i] = lb[i] + rb[i];
  for (int i = gid; i < 256*1024; i += gsz){ int k = i >> 10, j = i & 1023; g_Wm0[i] = l0w[j*256 + k]; }
  for (int i = gid; i < 1024*1024; i += gsz){ int k = i >> 10, j = i & 1023; g_Wm1[i] = l1w[j*1024 + k]; }
  for (int i = gid; i < BN*MM*HD; i += gsz) g_V[i] = 0.f;
  for (int i = gid; i < BN*MM; i += gsz) g_s[i] = 0.f;
  for (int i = gid; i < BN*HD; i += gsz) g_c[i] = 0.f;
  __nv_bfloat16 z = __float2bfloat16(0.f);
  for (int i = gid; i < 512*128; i += gsz){ g_Aph[i] = z; g_Apl[i] = z; }
  for (int i = gid; i < 256*128; i += gsz){ g_A2ph[i] = z; g_A2pl[i] = z; }
}

// ------------- bf16 tensor-core GEMM with 2-split compensation -------------
// D[j][b] = sum_k W[j][k] * Act[k][b];  CTA tile 64j x 64b x 128k.
// W: A-operand, row-major [j][k]. Act: packed [k/2][2*b + (k&1)].
// Partials: P[(ks*64 + b)*J + j].
template<int J, int K, int NKS>
__device__ __forceinline__ void gemm_mma(const __nv_bfloat16* __restrict__ Wh,
                                         const __nv_bfloat16* __restrict__ Wl,
                                         const __nv_bfloat16* __restrict__ Bh,
                                         const __nv_bfloat16* __restrict__ Bl,
                                         float* __restrict__ P){
  constexpr int KSL = K / NKS;        // 128
  constexpr int NCH = KSL / 32;       // 4 chunks of 32 k
  const int jt = blockIdx.x / NKS, ks = blockIdx.x % NKS;
  const int j0 = jt*64, k0 = ks*KSL;

  __shared__ __nv_bfloat16 sWh[2][64*40], sWl[2][64*40];     // stride 40 (pad)
  __shared__ __nv_bfloat16 sBh[2][16*144], sBl[2][16*144];   // stride 144 (pad)

  const int tid = threadIdx.x;
  const int w = tid >> 5, l = tid & 31, g = l >> 2, qi = l & 3;
  const int jw = (w & 3)*16, bw = (w >> 2)*32;

  const int jrow = tid >> 2, kq = tid & 3;     // W staging: 64 rows x 4x8 bf16
  const int brow = tid >> 4, bo = tid & 15;    // B staging: 16 rows x 16x8 bf16

  const __nv_bfloat16* gWh = Wh + (size_t)(j0 + jrow)*K + k0 + kq*8;
  const __nv_bfloat16* gWl = Wl + (size_t)(j0 + jrow)*K + k0 + kq*8;
  const __nv_bfloat16* gBh = Bh + (size_t)(k0/2 + brow)*128 + bo*8;
  const __nv_bfloat16* gBl = Bl + (size_t)(k0/2 + brow)*128 + bo*8;

  uint4 rwh = *(const uint4*)gWh;
  uint4 rwl = *(const uint4*)gWl;
  uint4 rbh = *(const uint4*)gBh;
  uint4 rbl = *(const uint4*)gBl;

  float d[4][4];
  #pragma unroll
  for (int i = 0; i < 4; i++)
    #pragma unroll
    for (int j = 0; j < 4; j++) d[i][j] = 0.f;

  *(uint4*)&sWh[0][jrow*40 + kq*8] = rwh;
  *(uint4*)&sWl[0][jrow*40 + kq*8] = rwl;
  *(uint4*)&sBh[0][brow*144 + bo*8] = rbh;
  *(uint4*)&sBl[0][brow*144 + bo*8] = rbl;
  __syncthreads();

  #pragma unroll 1
  for (int c = 0; c < NCH; c++){
    const int p = c & 1;
    if (c + 1 < NCH){
      rwh = *(const uint4*)(gWh + (c+1)*32);
      rwl = *(const uint4*)(gWl + (c+1)*32);
      rbh = *(const uint4*)(gBh + (size_t)(c+1)*16*128);
      rbl = *(const uint4*)(gBl + (size_t)(c+1)*16*128);
    }
    #pragma unroll
    for (int s = 0; s < 2; s++){
      unsigned a0h = *(const unsigned*)&sWh[p][(jw+g  )*40 + s*16 + 2*qi];
      unsigned a1h = *(const unsigned*)&sWh[p][(jw+g+8)*40 + s*16 + 2*qi];
      unsigned a2h = *(const unsigned*)&sWh[p][(jw+g  )*40 + s*16 + 2*qi + 8];
      unsigned a3h = *(const unsigned*)&sWh[p][(jw+g+8)*40 + s*16 + 2*qi + 8];
      unsigned a0l = *(const unsigned*)&sWl[p][(jw+g  )*40 + s*16 + 2*qi];
      unsigned a1l = *(const unsigned*)&sWl[p][(jw+g+8)*40 + s*16 + 2*qi];
      unsigned a2l = *(const unsigned*)&sWl[p][(jw+g  )*40 + s*16 + 2*qi + 8];
      unsigned a3l = *(const unsigned*)&sWl[p][(jw+g+8)*40 + s*16 + 2*qi + 8];
      #pragma unroll
      for (int nt = 0; nt < 4; nt++){
        int n = bw + nt*8 + g;
        unsigned b0h = *(const unsigned*)&sBh[p][(s*8 + qi    )*144 + 2*n];
        unsigned b1h = *(const unsigned*)&sBh[p][(s*8 + 4 + qi)*144 + 2*n];
        unsigned b0l = *(const unsigned*)&sBl[p][(s*8 + qi    )*144 + 2*n];
        unsigned b1l = *(const unsigned*)&sBl[p][(s*8 + 4 + qi)*144 + 2*n];
        MMA_BF16(d[nt], a0h,a1h,a2h,a3h, b0h,b1h);
        MMA_BF16(d[nt], a0h,a1h,a2h,a3h, b0l,b1l);
        MMA_BF16(d[nt], a0l,a1l,a2l,a3l, b0h,b1h);
      }
    }
    if (c + 1 < NCH){
      __syncthreads();
      *(uint4*)&sWh[1-p][jrow*40 + kq*8] = rwh;
      *(uint4*)&sWl[1-p][jrow*40 + kq*8] = rwl;
      *(uint4*)&sBh[1-p][brow*144 + bo*8] = rbh;
      *(uint4*)&sBl[1-p][brow*144 + bo*8] = rbl;
      __syncthreads();
    }
  }

  #pragma unroll
  for (int nt = 0; nt < 4; nt++){
    int b = bw + nt*8 + 2*qi;
    int jA = j0 + jw + g, jB = jA + 8;
    P[(size_t)(ks*64 + b    )*J + jA] = d[nt][0];
    P[(size_t)(ks*64 + b + 1)*J + jA] = d[nt][1];
    P[(size_t)(ks*64 + b    )*J + jB] = d[nt][2];
    P[(size_t)(ks*64 + b + 1)*J + jB] = d[nt][3];
  }
}

__global__ void __launch_bounds__(256,2) k_lstm(){
  gemm_mma<1024,1024,8>(g_Wfh, g_Wfl, g_Aph, g_Apl, g_Gp);
}
__global__ void __launch_bounds__(256,2) k_tree(){
  gemm_mma<1280,512,4>(g_Wth, g_Wtl, g_A2ph, g_A2pl, g_Tp);
}

// ------------- pointwise: gates, alphas, popping reads -------------
__global__ void __launch_bounds__(256) k_point(int t, int m0, const float* __restrict__ aw,
                                               const float* __restrict__ ab){
  int b = blockIdx.x, tid = threadIdx.x, warp = tid >> 5, lane = tid & 31;
  __shared__ float sg[1024], w1[224], wt[224], wb[64], red[16];
  __shared__ float s_ar;
  __shared__ int mEnd, bEnd;
  if (tid == 0){ mEnd = m0; bEnd = 0; }
  for (int j = tid; j < 1024; j += 256){
    float v = g_bf[j];
    #pragma unroll
    for (int ks = 0; ks < 8; ks++) v += g_Gp[(size_t)(ks*64 + b)*1024 + j];
    sg[j] = v;
  }
  __syncthreads();
  {
    int h = tid;
    float gi = sg[h], gf = sg[256+h], gg = sg[512+h], go = sg[768+h];
    float c = g_c[b*HD + h];
    c = sigf(gf)*c + sigf(gi)*tanhf(gg);
    float hh = sigf(go)*tanhf(c);
    g_c[b*HD + h] = c;
    packAct(g_Aph, g_Apl, 768 + h, b, hh);
    float p0 = hh*aw[h], p1 = hh*aw[256+h];
    #pragma unroll
    for (int o = 16; o >= 1; o >>= 1){
      p0 += __shfl_xor_sync(0xffffffffu, p0, o);
      p1 += __shfl_xor_sync(0xffffffffu, p1, o);
    }
    if (lane == 0){ red[warp] = p0; red[8+warp] = p1; }
  }
  __syncthreads();
  if (tid == 0){
    float d0 = ab[0], d1 = ab[1];
    for (int w = 0; w < 8; w++){ d0 += red[w]; d1 += red[8+w]; }
    s_ar = sigf(10.f*(d0 - d1));
  }
  __syncthreads();
  float ar = s_ar, as = 1.f - ar;
  int idx = 191 - 2*t, idx2 = 190 - 2*t;
  if (warp == 0){
    scan_stack(&g_s[b*MM], ar, w1, wt, true, &mEnd);
    if (lane == 0){ g_s[b*MM + idx] = ar; g_s[b*MM + idx2] = as; }
  } else if (warp == 1){
    scan_buf(&g_sb[b*SEQ], as, wb, true, &bEnd);
  }
  __syncthreads();
  {
    int h = tid;
    int me = mEnd, be = bEnd;
    float r1 = 0.f, r2 = 0.f;
    const float* Vb = g_V + (b*MM)*HD + h;
    for (int m = m0; m < me; m++){
      float tw = wt[m];
      if (tw != 0.f){
        float v = Vb[m*HD];
        r1 = fmaf(w1[m], v, r1);
        r2 = fmaf(tw - w1[m], v, r2);
      }
    }
    packAct(g_A2ph, g_A2pl, h, b, r1);
    packAct(g_A2ph, g_A2pl, 256 + h, b, r2);
    g_r12[b*512 + h] = r1;
    g_r12[b*512 + 256 + h] = r2;
    float bv = 0.f;
    const float* Bb = g_B + (b*SEQ)*HD + h;
    for (int s2 = 0; s2 < be; s2++){
      float w = wb[s2];
      if (w != 0.f) bv = fmaf(w, Bb[s2*HD], bv);
    }
    g_V[(b*MM + idx2)*HD + h] = bv;
  }
}

// ------------- epilogue: tree cell + next-step alpha=1 reads -------------
__global__ void __launch_bounds__(256) k_epi(int t, int m0){
  int b = blockIdx.x, tid = threadIdx.x, warp = tid >> 5;
  __shared__ float stg[1280], w1[224], wt[224], wb[64];
  __shared__ int mEnd, bEnd;
  if (tid == 0){ mEnd = m0; bEnd = 0; }
  __syncthreads();
  if (t >= 0){
    for (int j = tid; j < 1280; j += 256){
      float v = g_bt[j];
      #pragma unroll
      for (int ks = 0; ks < 4; ks++) v += g_Tp[(size_t)(ks*64 + b)*1280 + j];
      stg[j] = v;
    }
    __syncthreads();
    int h = tid;
    float ta = stg[h], ti = stg[256+h], f1 = stg[512+h], f2 = stg[768+h], to = stg[1024+h];
    float r1 = g_r12[b*512 + h], r2 = g_r12[b*512 + 256 + h];
    float ct = tanhf(ta)*sigf(ti) + sigf(f1)*r1 + sigf(f2)*r2;
    float ht = sigf(to)*tanhf(ct);
    g_V[(b*MM + (191 - 2*t))*HD + h] = ht;
    __syncthreads();
  }
  if (warp == 0) scan_stack(&g_s[b*MM], 1.f, w1, wt, false, &mEnd);
  else if (warp == 1) scan_buf(&g_sb[b*SEQ], 1.f, wb, false, &bEnd);
  __syncthreads();
  int h = tid;
  int me = mEnd, be = bEnd;
  float xb = 0.f;
  const float* Bb = g_B + (b*SEQ)*HD + h;
  for (int s2 = 0; s2 < be; s2++){
    float w = wb[s2];
    if (w != 0.f) xb = fmaf(w, Bb[s2*HD], xb);
  }
  float x1 = 0.f, x2 = 0.f;
  const float* Vb = g_V + (b*MM)*HD + h;
  for (int m = m0; m < me; m++){
    float tw = wt[m];
    if (tw != 0.f){
      float v = Vb[m*HD];
      x1 = fmaf(w1[m], v, x1);
      x2 = fmaf(tw - w1[m], v, x2);
    }
  }
  packAct(g_Aph, g_Apl, h,       b, xb);
  packAct(g_Aph, g_Apl, 256 + h, b, x1);
  packAct(g_Aph, g_Apl, 512 + h, b, x2);
  g_x1f[b*HD + h] = x1;
}

// ------------- MLP head -------------
__global__ void __launch_bounds__(256) k_mlp0(const float* __restrict__ l0b){
  int b = blockIdx.x, tid = threadIdx.x;
  __shared__ float xs[256];
  xs[tid] = g_x1f[b*HD + tid];
  __syncthreads();
  float4 acc = *(const float4*)&l0b[4*tid];
  for (int k = 0; k < 256; k++){
    float4 w = *(const float4*)&g_Wm0[k*1024 + 4*tid];
    float x = xs[k];
    acc.x = fmaf(x, w.x, acc.x); acc.y = fmaf(x, w.y, acc.y);
    acc.z = fmaf(x, w.z, acc.z); acc.w = fmaf(x, w.w, acc.w);
  }
  acc.x = fmaxf(acc.x, 0.f); acc.y = fmaxf(acc.y, 0.f);
  acc.z = fmaxf(acc.z, 0.f); acc.w = fmaxf(acc.w, 0.f);
  *(float4*)&g_y0[b*1024 + 4*tid] = acc;
}

__global__ void __launch_bounds__(256) k_mlp1(const float* __restrict__ l1b){
  int b = blockIdx.x, tid = threadIdx.x;
  __shared__ float xs[1024];
  for (int i = tid; i < 1024; i += 256) xs[i] = g_y0[b*1024 + i];
  __syncthreads();
  float4 acc = *(const float4*)&l1b[4*tid];
  for (int k = 0; k < 1024; k++){
    float4 w = *(const float4*)&g_Wm1[k*1024 + 4*tid];
    float x = xs[k];
    acc.x = fmaf(x, w.x, acc.x); acc.y = fmaf(x, w.y, acc.y);
    acc.z = fmaf(x, w.z, acc.z); acc.w = fmaf(x, w.w, acc.w);
  }
  acc.x = fmaxf(acc.x, 0.f); acc.y = fmaxf(acc.y, 0.f);
  acc.z = fmaxf(acc.z, 0.f); acc.w = fmaxf(acc.w, 0.f);
  *(float4*)&g_y1[b*1024 + 4*tid] = acc;
}

__global__ void __launch_bounds__(256) k_mlp2(const float* __restrict__ l2w,
                                              const float* __restrict__ l2b,
                                              float* __restrict__ out){
  int b = blockIdx.x, tid = threadIdx.x, warp = tid >> 5, lane = tid & 31;
  __shared__ float red[8];
  for (int c = 0; c < 3; c++){
    float p = 0.f;
    for (int k = tid; k < 1024; k += 256)
      p = fmaf(g_y1[b*1024 + k], l2w[c*1024 + k], p);
    #pragma unroll
    for (int o = 16; o >= 1; o >>= 1) p += __shfl_xor_sync(0xffffffffu, p, o);
    if (lane == 0) red[warp] = p;
    __syncthreads();
    if (tid == 0){
      float s = l2b[c];
      for (int w = 0; w < 8; w++) s += red[w];
      out[b*3 + c] = s;
    }
    __syncthreads();
  }
}

// ------------- launch -------------
extern "C" void kernel_launch(void* const* d_in, const int* in_sizes, int n_in,
                              void* d_out, int out_size){
  const void*  x   = d_in[0];
  const float* emb = (const float*)d_in[1];
  const float* wih = (const float*)d_in[2];
  const float* whh = (const float*)d_in[3];
  const float* bih = (const float*)d_in[4];
  const float* bhh = (const float*)d_in[5];
  const float* aw  = (const float*)d_in[6];
  const float* ab  = (const float*)d_in[7];
  const float* lw  = (const float*)d_in[8];
  const float* lb  = (const float*)d_in[9];
  const float* rw  = (const float*)d_in[10];
  const float* rb  = (const float*)d_in[11];
  const float* l0w = (const float*)d_in[12];
  const float* l0b = (const float*)d_in[13];
  const float* l1w = (const float*)d_in[14];
  const float* l1b = (const float*)d_in[15];
  const float* l2w = (const float*)d_in[16];
  const float* l2b = (const float*)d_in[17];
  float* out = (float*)d_out;

  k_tok<<<1, 256>>>(x);
  k_prep<<<512, 256>>>(x, emb, wih, whh, bih, bhh, lw, lb, rw, rb, l0w, l1w);
  k_epi<<<64, 256>>>(-1, 192);
  for (int t = 0; t < TSTEPS; t++){
    int m0p = 192 - 2*t; if (m0p < 0) m0p = 0;
    int m0e = 190 - 2*t; if (m0e < 0) m0e = 0;
    k_lstm<<<128, 256>>>();
    k_point<<<64, 256>>>(t, m0p, aw, ab);
    k_tree<<<80, 256>>>();
    k_epi<<<64, 256>>>(t, m0e);
  }
  k_mlp0<<<64, 256>>>(l0b);
  k_mlp1<<<64, 256>>>(l1b);
  k_mlp2<<<64, 256>>>(l2w, l2b, out);
}